// round 4
// baseline (speedup 1.0000x reference)
#include <cuda_runtime.h>
#include <math.h>
#include <float.h>

#define NN 50000
#define NE 800000
#define FF 10
#define TT 5
#define TF 50
#define GG 64

// ---------------- device scratch --------------------------------------------
static __device__ int      d_deg[NN];
static __device__ int      d_offs[NN + 1];
static __device__ int      d_cursor[NN];
static __device__ unsigned d_csr[NE];          // src (bits 0..27) | attr<<28
static __device__ float    d_h[NN * FF];
static __device__ float    d_p[NN * TF];
static __device__ float    d_q[NN * TF];
static __device__ float    d_o[NN * FF];
static __device__ float    d_amp[NN];
static __device__ float    d_att[NN];
static __device__ float    d_invd[NN];
static __device__ float    d_c3[4 * TF];
static __device__ float    d_bn[2 * FF];
static __device__ float    d_avglog;
static __device__ float    d_pool[GG * FF];

// ---------------- kernels ---------------------------------------------------
__global__ void k_zero() {
    int i = blockIdx.x * blockDim.x + threadIdx.x;
    if (i < NN) { d_deg[i] = 0; d_cursor[i] = 0; }
    if (i < GG * FF) d_pool[i] = 0.f;
}

__global__ void k_deg(const int* __restrict__ ei) {
    int i = blockIdx.x * blockDim.x + threadIdx.x;
    if (i >= NE) return;
    int dst = ei[NE + i];
    if (dst >= 0 && dst < NN) atomicAdd(&d_deg[dst], 1);
}

// single block: exclusive scan of deg -> offs, plus mean(log(deg+1))
__global__ void k_scan() {
    __shared__ int   s_cnt[1024];
    __shared__ float s_log[1024];
    const int tid = threadIdx.x;
    const int CH = 49;                       // 49*1024 >= 50000
    int base = tid * CH;
    int cnt = 0; float ls = 0.f;
    for (int k = 0; k < CH; k++) {
        int idx = base + k;
        if (idx < NN) {
            int dg = d_deg[idx];
            cnt += dg;
            ls += logf((float)dg + 1.f);
        }
    }
    s_cnt[tid] = cnt;
    s_log[tid] = ls;
    __syncthreads();
    for (int off = 1; off < 1024; off <<= 1) {
        int v = (tid >= off) ? s_cnt[tid - off] : 0;
        __syncthreads();
        s_cnt[tid] += v;
        __syncthreads();
    }
    int run = s_cnt[tid] - cnt;
    for (int k = 0; k < CH; k++) {
        int idx = base + k;
        if (idx < NN) {
            d_offs[idx] = run;
            run += d_deg[idx];
        }
    }
    if (tid == 0) d_offs[NN] = NE;
    __syncthreads();
    for (int off = 512; off > 0; off >>= 1) {
        if (tid < off) s_log[tid] += s_log[tid + off];
        __syncthreads();
    }
    if (tid == 0) d_avglog = s_log[0] / (float)NN;
}

__global__ void k_coef() {
    int n = blockIdx.x * blockDim.x + threadIdx.x;
    if (n >= NN) return;
    float avg = d_avglog;
    float dg = (float)d_deg[n];
    float d  = fmaxf(dg, 1.f);
    float ld = logf(d + 1.f);
    d_amp[n]  = ld / avg;
    d_att[n]  = avg / ld;
    d_invd[n] = 1.f / d;
}

__global__ void k_fill(const int* __restrict__ ei,
                       const int* __restrict__ eattr) {
    int i = blockIdx.x * blockDim.x + threadIdx.x;
    if (i >= NE) return;
    int src  = ei[i];
    int dst  = ei[NE + i];
    int attr = eattr[i] & 3;
    if (dst < 0 || dst >= NN) return;
    if (src < 0 || src >= NN) src = 0;
    int pos = atomicAdd(&d_cursor[dst], 1);
    int slot = d_offs[dst] + pos;
    if (slot >= 0 && slot < NE)
        d_csr[slot] = (unsigned)src | ((unsigned)attr << 28);
}

__global__ void k_mlp1(const float* __restrict__ x,
                       const float* __restrict__ w1, const float* __restrict__ b1,
                       const float* __restrict__ w2, const float* __restrict__ b2) {
    int n = blockIdx.x * blockDim.x + threadIdx.x;
    if (n >= NN) return;
    float xv[FF];
#pragma unroll
    for (int k = 0; k < FF; k++) xv[k] = x[n * FF + k];
    float hid[5];
#pragma unroll
    for (int j = 0; j < 5; j++) {
        float a = __ldg(&b1[j]);
#pragma unroll
        for (int k = 0; k < FF; k++) a += xv[k] * __ldg(&w1[k * 5 + j]);
        hid[j] = fmaxf(a, 0.f);
    }
#pragma unroll
    for (int f = 0; f < FF; f++) {
        float a = __ldg(&b2[f]);
#pragma unroll
        for (int j = 0; j < 5; j++) a += hid[j] * __ldg(&w2[j * FF + f]);
        d_h[n * FF + f] = a;
    }
}

// per-layer edge-attr table: c3[a][t][f] = (edge_emb[a]@enc_w+enc_b)@W3_t + pre_b_t
__global__ void k_etab(const float* __restrict__ eemb,
                       const float* __restrict__ encw, const float* __restrict__ encb,
                       const float* __restrict__ prew, const float* __restrict__ preb,
                       int l) {
    __shared__ float e4[4 * FF];
    int tid = threadIdx.x;
    if (tid < 4 * FF) {
        int a = tid / FF, k = tid % FF;
        float v = encb[l * FF + k];
        for (int j = 0; j < FF; j++)
            v += eemb[a * FF + j] * encw[(l * FF + j) * FF + k];
        e4[tid] = v;
    }
    if (tid < 2 * FF) d_bn[tid] = 0.f;      // reset BN accumulators for this layer
    __syncthreads();
    if (tid < 4 * TF) {
        int a = tid / TF, tf = tid % TF, t = tf / FF, f = tf % FF;
        float v = preb[(l * TT + t) * FF + f];
        for (int k = 0; k < FF; k++)
            v += e4[a * FF + k] * prew[((l * TT + t) * 3 * FF + 2 * FF + k) * FF + f];
        d_c3[tid] = v;
    }
}

// p[n,t,f] = h[n] @ pre_w[l,t,0:F,:] ; q uses rows F:2F
__global__ void k_pq(const float* __restrict__ prew, int l) {
    int n = blockIdx.x * blockDim.x + threadIdx.x;
    if (n >= NN) return;
    float hv[FF];
#pragma unroll
    for (int k = 0; k < FF; k++) hv[k] = d_h[n * FF + k];
    for (int t = 0; t < TT; t++) {
        const float* W = prew + (size_t)(l * TT + t) * 3 * FF * FF;
#pragma unroll
        for (int f = 0; f < FF; f++) {
            float ap = 0.f, aq = 0.f;
#pragma unroll
            for (int k = 0; k < FF; k++) {
                ap += hv[k] * __ldg(&W[k * FF + f]);
                aq += hv[k] * __ldg(&W[(FF + k) * FF + f]);
            }
            d_p[n * TF + t * FF + f] = ap;
            d_q[n * TF + t * FF + f] = aq;
        }
    }
}

// warp-per-node: edge gather + PNA stats + post/lin matmuls + BN partial sums
__global__ void __launch_bounds__(256) k_agg(const float* __restrict__ postw,
                                             const float* __restrict__ postb,
                                             const float* __restrict__ linw,
                                             const float* __restrict__ linb,
                                             int l) {
    __shared__ float sh_c3[4 * TF];
    __shared__ float sh_pw[TT * 130 * 2];
    __shared__ float sh_pb[TT * 2];
    __shared__ float sh_lw[FF * FF];
    __shared__ float sh_lb[FF];
    __shared__ float sh_xt[8][FF];
    __shared__ float sh_st[8][TF][4];
    __shared__ float sh_o10[8][FF];
    __shared__ float sh_bna[2 * FF];
    const int tid = threadIdx.x;
    for (int i = tid; i < 4 * TF; i += 256) sh_c3[i] = d_c3[i];
    for (int i = tid; i < TT * 130 * 2; i += 256) sh_pw[i] = postw[l * TT * 130 * 2 + i];
    if (tid < TT * 2) sh_pb[tid] = postb[l * TT * 2 + tid];
    for (int i = tid; i < FF * FF; i += 256) sh_lw[i] = linw[l * FF * FF + i];
    if (tid < FF) sh_lb[tid] = linb[l * FF + tid];
    if (tid < 2 * FF) sh_bna[tid] = 0.f;
    __syncthreads();

    const int w = tid >> 5, lane = tid & 31;
    const int n = blockIdx.x * 8 + w;
    if (n < NN) {
        const float amp = d_amp[n], att = d_att[n], invd = d_invd[n];
        const int dg = d_deg[n];
        if (lane < FF) sh_xt[w][lane] = d_h[n * FF + lane];
        const int f0 = lane, f1 = lane + 32;
        const bool h1 = (f1 < TF);
        const float p0 = d_p[n * TF + f0];
        const float p1 = h1 ? d_p[n * TF + f1] : 0.f;
        float s0 = 0.f, ss0 = 0.f, mn0 = FLT_MAX, mx0 = -FLT_MAX;
        float s1 = 0.f, ss1 = 0.f, mn1 = FLT_MAX, mx1 = -FLT_MAX;
        const int st = d_offs[n], en = d_offs[n + 1];
        for (int i = st; i < en; i++) {
            unsigned pk = d_csr[i];
            int src = (int)(pk & 0x0FFFFFFFu);
            int a = (int)(pk >> 28);
            float m0 = p0 + __ldg(&d_q[src * TF + f0]) + sh_c3[a * TF + f0];
            s0 += m0; ss0 += m0 * m0;
            mn0 = fminf(mn0, m0); mx0 = fmaxf(mx0, m0);
            if (h1) {
                float m1 = p1 + __ldg(&d_q[src * TF + f1]) + sh_c3[a * TF + f1];
                s1 += m1; ss1 += m1 * m1;
                mn1 = fminf(mn1, m1); mx1 = fmaxf(mx1, m1);
            }
        }
        {
            float mean0 = s0 * invd;
            float std0 = sqrtf(fmaxf(ss0 * invd - mean0 * mean0, 0.f) + 1e-5f);
            sh_st[w][f0][0] = mean0;
            sh_st[w][f0][1] = (dg > 0) ? mn0 : 0.f;
            sh_st[w][f0][2] = (dg > 0) ? mx0 : 0.f;
            sh_st[w][f0][3] = std0;
            if (h1) {
                float mean1 = s1 * invd;
                float std1 = sqrtf(fmaxf(ss1 * invd - mean1 * mean1, 0.f) + 1e-5f);
                sh_st[w][f1][0] = mean1;
                sh_st[w][f1][1] = (dg > 0) ? mn1 : 0.f;
                sh_st[w][f1][2] = (dg > 0) ? mx1 : 0.f;
                sh_st[w][f1][3] = std1;
            }
        }
        __syncwarp();
        if (lane < TT * 2) {                 // 10 lanes: (t,j) of post matmul
            int t = lane >> 1, j = lane & 1;
            float acc = sh_pb[t * 2 + j];
#pragma unroll
            for (int f = 0; f < FF; f++)
                acc += sh_xt[w][f] * sh_pw[(t * 130 + f) * 2 + j];
#pragma unroll
            for (int s = 0; s < 4; s++) {
#pragma unroll
                for (int f = 0; f < FF; f++) {
                    float sv = sh_st[w][t * FF + f][s];
                    int rb = 10 + s * 10 + f;
                    acc += sv * (sh_pw[(t * 130 + rb) * 2 + j]
                               + amp * sh_pw[(t * 130 + rb + 40) * 2 + j]
                               + att * sh_pw[(t * 130 + rb + 80) * 2 + j]);
                }
            }
            sh_o10[w][lane] = acc;
        }
        __syncwarp();
        if (lane < FF) {                     // lin layer + BN partials
            float v = sh_lb[lane];
#pragma unroll
            for (int i = 0; i < FF; i++) v += sh_o10[w][i] * sh_lw[i * FF + lane];
            d_o[n * FF + lane] = v;
            atomicAdd(&sh_bna[lane], v);
            atomicAdd(&sh_bna[FF + lane], v * v);
        }
    }
    __syncthreads();
    if (tid < 2 * FF) atomicAdd(&d_bn[tid], sh_bna[tid]);
}

__global__ void k_bn(const float* __restrict__ gamma, const float* __restrict__ beta,
                     const int* __restrict__ batch, int l, int last) {
    int n = blockIdx.x * blockDim.x + threadIdx.x;
    if (n >= NN) return;
    int b = 0;
    if (last) {
        b = batch[n];
        if (b < 0) b = 0;
        if (b >= GG) b = GG - 1;
    }
#pragma unroll
    for (int f = 0; f < FF; f++) {
        float mu  = d_bn[f] / (float)NN;
        float var = d_bn[FF + f] / (float)NN - mu * mu;
        float inv = rsqrtf(var + 1e-5f);
        float v = (d_o[n * FF + f] - mu) * inv * __ldg(&gamma[l * FF + f]) + __ldg(&beta[l * FF + f]);
        v = fmaxf(v, 0.f);
        d_h[n * FF + f] = v;
        if (last) atomicAdd(&d_pool[b * FF + f], v);
    }
}

__global__ void k_final(const float* __restrict__ w1, const float* __restrict__ b1,
                        const float* __restrict__ w2, const float* __restrict__ b2,
                        float* __restrict__ out) {
    int g = threadIdx.x;
    if (g >= GG) return;
    float pv[FF];
#pragma unroll
    for (int k = 0; k < FF; k++) pv[k] = d_pool[g * FF + k];
    float o = b2[0];
#pragma unroll
    for (int j = 0; j < 5; j++) {
        float hj = b1[j];
#pragma unroll
        for (int k = 0; k < FF; k++) hj += pv[k] * w1[k * 5 + j];
        o += fmaxf(hj, 0.f) * w2[j];
    }
    out[g] = o;
}

// ---------------- launch -----------------------------------------------------
extern "C" void kernel_launch(void* const* d_in, const int* in_sizes, int n_in,
                              void* d_out, int out_size) {
    const float* x        = (const float*)d_in[0];
    const float* edge_emb = (const float*)d_in[1];
    const float* mlp1_w1  = (const float*)d_in[2];
    const float* mlp1_b1  = (const float*)d_in[3];
    const float* mlp1_w2  = (const float*)d_in[4];
    const float* mlp1_b2  = (const float*)d_in[5];
    const float* enc_w    = (const float*)d_in[6];
    const float* enc_b    = (const float*)d_in[7];
    const float* pre_w    = (const float*)d_in[8];
    const float* pre_b    = (const float*)d_in[9];
    const float* post_w   = (const float*)d_in[10];
    const float* post_b   = (const float*)d_in[11];
    const float* lin_w    = (const float*)d_in[12];
    const float* lin_b    = (const float*)d_in[13];
    const float* bn_gamma = (const float*)d_in[14];
    const float* bn_beta  = (const float*)d_in[15];
    const float* mlp2_w1  = (const float*)d_in[16];
    const float* mlp2_b1  = (const float*)d_in[17];
    const float* mlp2_w2  = (const float*)d_in[18];
    const float* mlp2_b2  = (const float*)d_in[19];
    const int* edge_index = (const int*)d_in[20];
    const int* edge_attr  = (const int*)d_in[21];
    const int* batch      = (const int*)d_in[22];
    float* out = (float*)d_out;

    const int TB = 256;
    k_zero<<<(NN + TB - 1) / TB, TB>>>();
    k_deg<<<(NE + TB - 1) / TB, TB>>>(edge_index);
    k_scan<<<1, 1024>>>();
    k_coef<<<(NN + TB - 1) / TB, TB>>>();
    k_fill<<<(NE + TB - 1) / TB, TB>>>(edge_index, edge_attr);
    k_mlp1<<<(NN + TB - 1) / TB, TB>>>(x, mlp1_w1, mlp1_b1, mlp1_w2, mlp1_b2);
    for (int l = 0; l < 2; l++) {
        k_etab<<<1, 256>>>(edge_emb, enc_w, enc_b, pre_w, pre_b, l);
        k_pq<<<(NN + TB - 1) / TB, TB>>>(pre_w, l);
        k_agg<<<(NN + 7) / 8, 256>>>(post_w, post_b, lin_w, lin_b, l);
        k_bn<<<(NN + TB - 1) / TB, TB>>>(bn_gamma, bn_beta, batch, l, l == 1);
    }
    k_final<<<1, 64>>>(mlp2_w1, mlp2_b1, mlp2_w2, mlp2_b2, out);
}

// round 5
// speedup vs baseline: 1.0668x; 1.0668x over previous
#include <cuda_runtime.h>
#include <math.h>
#include <float.h>

#define NN 50000
#define NE 800000
#define FF 10
#define TT 5
#define TF 50
#define QP 64          // padded row stride for d_p / d_q (256B-aligned rows)
#define GG 64

// ---------------- device scratch --------------------------------------------
static __device__ int      d_deg[NN];
static __device__ int      d_offs[NN + 1];
static __device__ int      d_cursor[NN];
static __device__ unsigned d_csr[NE];          // src (bits 0..27) | attr<<28
static __device__ float    d_h[NN * FF];
static __device__ __align__(256) float d_p[NN * QP];   // pads never written -> stay 0
static __device__ __align__(256) float d_q[NN * QP];
static __device__ float    d_o[NN * FF];
static __device__ float    d_amp[NN];
static __device__ float    d_att[NN];
static __device__ float    d_invd[NN];
static __device__ float    d_c3[4 * TF];
static __device__ float    d_bn[2 * FF];
static __device__ float    d_pool[GG * FF];

// ---------------- kernels ---------------------------------------------------
__global__ void k_zero() {
    int i = blockIdx.x * blockDim.x + threadIdx.x;
    if (i < NN) { d_deg[i] = 0; d_cursor[i] = 0; }
    if (i < GG * FF) d_pool[i] = 0.f;
}

__global__ void k_deg(const int* __restrict__ ei) {
    int i = blockIdx.x * blockDim.x + threadIdx.x;
    if (i >= NE) return;
    int dst = ei[NE + i];
    if (dst >= 0 && dst < NN) atomicAdd(&d_deg[dst], 1);
}

// single block: coalesced warp-chunked scan of deg -> offs, avg log, PNA coefs
__global__ void k_scan() {
    __shared__ int   s_wcnt[32];
    __shared__ float s_wlog[32];
    __shared__ float s_avg;
    const int tid = threadIdx.x, lane = tid & 31, wp = tid >> 5;
    const int base = wp * 1568;                 // 32 warps * 1568 >= 50000
    // phase A: per-warp totals with coalesced loads
    int csum = 0; float lsum = 0.f;
    for (int j = 0; j < 49; j++) {
        int idx = base + j * 32 + lane;
        if (idx < NN) {
            int dg = d_deg[idx];
            csum += dg;
            lsum += logf((float)dg + 1.f);
        }
    }
    for (int o = 16; o; o >>= 1) {
        csum += __shfl_xor_sync(0xffffffffu, csum, o);
        lsum += __shfl_xor_sync(0xffffffffu, lsum, o);
    }
    if (lane == 0) { s_wcnt[wp] = csum; s_wlog[wp] = lsum; }
    __syncthreads();
    if (wp == 0) {
        int v = s_wcnt[lane];
        float lg = s_wlog[lane];
        int inc = v;
        for (int o = 1; o < 32; o <<= 1) {
            int u = __shfl_up_sync(0xffffffffu, inc, o);
            if (lane >= o) inc += u;
        }
        s_wcnt[lane] = inc - v;                 // exclusive warp base
        for (int o = 16; o; o >>= 1) lg += __shfl_xor_sync(0xffffffffu, lg, o);
        if (lane == 0) s_avg = lg / (float)NN;
    }
    __syncthreads();
    const float avg = s_avg;
    int run = s_wcnt[wp];
    for (int j = 0; j < 49; j++) {
        int idx = base + j * 32 + lane;
        int dg = (idx < NN) ? d_deg[idx] : 0;
        int inc = dg;
        for (int o = 1; o < 32; o <<= 1) {
            int u = __shfl_up_sync(0xffffffffu, inc, o);
            if (lane >= o) inc += u;
        }
        if (idx < NN) {
            d_offs[idx] = run + inc - dg;
            float d = fmaxf((float)dg, 1.f);
            float ld = logf(d + 1.f);
            d_amp[idx]  = ld / avg;
            d_att[idx]  = avg / ld;
            d_invd[idx] = 1.f / d;
        }
        run += __shfl_sync(0xffffffffu, inc, 31);
    }
    if (tid == 0) d_offs[NN] = NE;
}

__global__ void k_fill(const int* __restrict__ ei, const int* __restrict__ eattr) {
    int i = blockIdx.x * blockDim.x + threadIdx.x;
    if (i >= NE) return;
    int src  = ei[i];
    int dst  = ei[NE + i];
    int attr = eattr[i] & 3;
    if (dst < 0 || dst >= NN) return;
    if (src < 0 || src >= NN) src = 0;
    int pos = atomicAdd(&d_cursor[dst], 1);
    int slot = d_offs[dst] + pos;
    if (slot >= 0 && slot < NE)
        d_csr[slot] = (unsigned)src | ((unsigned)attr << 28);
}

// per-layer edge-attr table + BN accumulator reset
__global__ void k_etab(const float* __restrict__ eemb,
                       const float* __restrict__ encw, const float* __restrict__ encb,
                       const float* __restrict__ prew, const float* __restrict__ preb,
                       int l) {
    __shared__ float e4[4 * FF];
    int tid = threadIdx.x;
    if (tid < 4 * FF) {
        int a = tid / FF, k = tid % FF;
        float v = encb[l * FF + k];
        for (int j = 0; j < FF; j++)
            v += eemb[a * FF + j] * encw[(l * FF + j) * FF + k];
        e4[tid] = v;
    }
    if (tid < 2 * FF) d_bn[tid] = 0.f;
    __syncthreads();
    if (tid < 4 * TF) {
        int a = tid / TF, tf = tid % TF, t = tf / FF, f = tf % FF;
        float v = preb[(l * TT + t) * FF + f];
        for (int k = 0; k < FF; k++)
            v += e4[a * FF + k] * prew[((l * TT + t) * 3 * FF + 2 * FF + k) * FF + f];
        d_c3[tid] = v;
    }
}

// fused h-producer + p/q projection. mode 0: h=mlp1(x); mode 1: h=relu(BN_{l-1}(d_o))
// block = 4 nodes x 64 lanes; coalesced p/q stores.
__global__ void __launch_bounds__(256) k_pq(
    const float* __restrict__ x,
    const float* __restrict__ m1w1, const float* __restrict__ m1b1,
    const float* __restrict__ m1w2, const float* __restrict__ m1b2,
    const float* __restrict__ gamma, const float* __restrict__ beta,
    const float* __restrict__ prew, int l, int mode)
{
    __shared__ float sh_h[4][FF];
    const int tid = threadIdx.x;
    const int g = tid >> 6;
    const int tf = tid & 63;
    const int n = blockIdx.x * 4 + g;
    if (n < NN && tf < FF) {
        float v;
        if (mode == 0) {
            float acc = __ldg(&m1b2[tf]);
#pragma unroll
            for (int j = 0; j < 5; j++) {
                float hj = __ldg(&m1b1[j]);
#pragma unroll
                for (int k = 0; k < FF; k++)
                    hj = fmaf(__ldg(&x[n * FF + k]), __ldg(&m1w1[k * 5 + j]), hj);
                acc = fmaf(fmaxf(hj, 0.f), __ldg(&m1w2[j * FF + tf]), acc);
            }
            v = acc;
        } else {
            float mu  = d_bn[tf] / (float)NN;
            float var = d_bn[FF + tf] / (float)NN - mu * mu;
            v = (d_o[n * FF + tf] - mu) * rsqrtf(var + 1e-5f)
                * __ldg(&gamma[(l - 1) * FF + tf]) + __ldg(&beta[(l - 1) * FF + tf]);
            v = fmaxf(v, 0.f);
        }
        sh_h[g][tf] = v;
        d_h[n * FF + tf] = v;
    }
    __syncthreads();
    if (n >= NN || tf >= TF) return;
    const int t = tf / FF, f = tf % FF;
    const float* W = prew + (size_t)(l * TT + t) * 3 * FF * FF;
    float ap = 0.f, aq = 0.f;
#pragma unroll
    for (int k = 0; k < FF; k++) {
        float hk = sh_h[g][k];
        ap = fmaf(hk, __ldg(&W[k * FF + f]), ap);
        aq = fmaf(hk, __ldg(&W[(FF + k) * FF + f]), aq);
    }
    d_p[n * QP + tf] = ap;
    d_q[n * QP + tf] = aq;
}

#define UPD0(m) { s0 += (m); ss0 = fmaf((m),(m),ss0); mn0 = fminf(mn0,(m)); mx0 = fmaxf(mx0,(m)); }
#define UPD1(m) { s1 += (m); ss1 = fmaf((m),(m),ss1); mn1 = fminf(mn1,(m)); mx1 = fmaxf(mx1,(m)); }

// warp-per-node: unrolled edge gather + PNA stats + warp-parallel post matvec + lin + BN sums
__global__ void __launch_bounds__(256) k_agg(const float* __restrict__ postw,
                                             const float* __restrict__ postb,
                                             const float* __restrict__ linw,
                                             const float* __restrict__ linb,
                                             int l) {
    __shared__ float sh_c3[4 * 64];              // padded to 64, pads = 0
    __shared__ float sh_pwT[10 * 130];           // [t*2+j][row]
    __shared__ float sh_pb[10];
    __shared__ float sh_lw[FF * FF];
    __shared__ float sh_lb[FF];
    __shared__ float sh_xt[8][FF];
    __shared__ float sh_st[8][4][TF];            // [warp][stat][tf]
    __shared__ float sh_o10[8][10];
    __shared__ float sh_bna[2 * FF];
    const int tid = threadIdx.x;
    { int a = tid >> 6, f = tid & 63; sh_c3[tid] = (f < TF) ? d_c3[a * TF + f] : 0.f; }
    for (int idx = tid; idx < 1300; idx += 256) {
        int t = idx / 260, rem = idx % 260, r = rem >> 1, j = rem & 1;
        sh_pwT[(t * 2 + j) * 130 + r] = postw[(l * TT + t) * 260 + rem];
    }
    if (tid < 10) sh_pb[tid] = postb[l * 10 + tid];
    if (tid < FF * FF) sh_lw[tid] = linw[l * FF * FF + tid];
    if (tid < FF) sh_lb[tid] = linb[l * FF + tid];
    if (tid < 2 * FF) sh_bna[tid] = 0.f;
    __syncthreads();

    const int w = tid >> 5, lane = tid & 31;
    const int n = blockIdx.x * 8 + w;
    if (n < NN) {
        const float amp = d_amp[n], att = d_att[n], invd = d_invd[n];
        const int stt = d_offs[n], enn = d_offs[n + 1];
        const int dg = enn - stt;
        if (lane < FF) sh_xt[w][lane] = d_h[n * FF + lane];
        const int f0 = lane, f1 = lane + 32;
        const float p0 = d_p[n * QP + f0];
        const float p1 = d_p[n * QP + f1];
        float s0 = 0.f, ss0 = 0.f, mn0 = FLT_MAX, mx0 = -FLT_MAX;
        float s1 = 0.f, ss1 = 0.f, mn1 = FLT_MAX, mx1 = -FLT_MAX;
        int i = stt;
        for (; i + 4 <= enn; i += 4) {
            unsigned pk0 = d_csr[i], pk1 = d_csr[i + 1], pk2 = d_csr[i + 2], pk3 = d_csr[i + 3];
            const float* q0 = d_q + (size_t)(pk0 & 0x0FFFFFFFu) * QP;
            const float* q1 = d_q + (size_t)(pk1 & 0x0FFFFFFFu) * QP;
            const float* q2 = d_q + (size_t)(pk2 & 0x0FFFFFFFu) * QP;
            const float* q3 = d_q + (size_t)(pk3 & 0x0FFFFFFFu) * QP;
            float a00 = __ldg(q0 + f0), a01 = __ldg(q0 + f1);
            float a10 = __ldg(q1 + f0), a11 = __ldg(q1 + f1);
            float a20 = __ldg(q2 + f0), a21 = __ldg(q2 + f1);
            float a30 = __ldg(q3 + f0), a31 = __ldg(q3 + f1);
            float m;
            m = p0 + a00 + sh_c3[(pk0 >> 28) * 64 + f0]; UPD0(m);
            m = p1 + a01 + sh_c3[(pk0 >> 28) * 64 + f1]; UPD1(m);
            m = p0 + a10 + sh_c3[(pk1 >> 28) * 64 + f0]; UPD0(m);
            m = p1 + a11 + sh_c3[(pk1 >> 28) * 64 + f1]; UPD1(m);
            m = p0 + a20 + sh_c3[(pk2 >> 28) * 64 + f0]; UPD0(m);
            m = p1 + a21 + sh_c3[(pk2 >> 28) * 64 + f1]; UPD1(m);
            m = p0 + a30 + sh_c3[(pk3 >> 28) * 64 + f0]; UPD0(m);
            m = p1 + a31 + sh_c3[(pk3 >> 28) * 64 + f1]; UPD1(m);
        }
        for (; i < enn; i++) {
            unsigned pk = d_csr[i];
            const float* q = d_q + (size_t)(pk & 0x0FFFFFFFu) * QP;
            float m;
            m = p0 + __ldg(q + f0) + sh_c3[(pk >> 28) * 64 + f0]; UPD0(m);
            m = p1 + __ldg(q + f1) + sh_c3[(pk >> 28) * 64 + f1]; UPD1(m);
        }
        {
            float mean0 = s0 * invd, mean1 = s1 * invd;
            float std0 = sqrtf(fmaxf(ss0 * invd - mean0 * mean0, 0.f) + 1e-5f);
            float std1 = sqrtf(fmaxf(ss1 * invd - mean1 * mean1, 0.f) + 1e-5f);
            bool hin = dg > 0;
            sh_st[w][0][f0] = mean0;
            sh_st[w][1][f0] = hin ? mn0 : 0.f;
            sh_st[w][2][f0] = hin ? mx0 : 0.f;
            sh_st[w][3][f0] = std0;
            if (f1 < TF) {
                sh_st[w][0][f1] = mean1;
                sh_st[w][1][f1] = hin ? mn1 : 0.f;
                sh_st[w][2][f1] = hin ? mx1 : 0.f;
                sh_st[w][3][f1] = std1;
            }
        }
        __syncwarp();
        // warp-parallel post matvec: rows r0=lane (0..31), r1=lane+32 (32..49)
        const int r0 = lane, r1 = lane + 32;
        const bool x0 = (r0 < FF);
        const int s0i = (r0 - FF) / FF, f0i = (r0 - FF) % FF;     // valid when !x0
        const int s1i = (r1 - FF) / FF, f1i = (r1 - FF) % FF;
        const bool v1 = (r1 < TF);
#pragma unroll
        for (int t = 0; t < TT; t++) {
            float iv0 = x0 ? sh_xt[w][r0] : sh_st[w][s0i][t * FF + f0i];
            float iv1 = v1 ? sh_st[w][s1i][t * FF + f1i] : 0.f;
#pragma unroll
            for (int j = 0; j < 2; j++) {
                const float* P = &sh_pwT[(t * 2 + j) * 130];
                float w0 = P[r0];
                if (!x0) w0 = fmaf(amp, P[r0 + 40], fmaf(att, P[r0 + 80], w0));
                float acc = iv0 * w0;
                if (v1) {
                    float w1v = fmaf(amp, P[r1 + 40], fmaf(att, P[r1 + 80], P[r1]));
                    acc = fmaf(iv1, w1v, acc);
                }
                acc += __shfl_xor_sync(0xffffffffu, acc, 16);
                acc += __shfl_xor_sync(0xffffffffu, acc, 8);
                acc += __shfl_xor_sync(0xffffffffu, acc, 4);
                acc += __shfl_xor_sync(0xffffffffu, acc, 2);
                acc += __shfl_xor_sync(0xffffffffu, acc, 1);
                if (lane == 0) sh_o10[w][t * 2 + j] = acc + sh_pb[t * 2 + j];
            }
        }
        __syncwarp();
        if (lane < FF) {
            float v = sh_lb[lane];
#pragma unroll
            for (int i2 = 0; i2 < FF; i2++)
                v = fmaf(sh_o10[w][i2], sh_lw[i2 * FF + lane], v);
            d_o[n * FF + lane] = v;
            atomicAdd(&sh_bna[lane], v);
            atomicAdd(&sh_bna[FF + lane], v * v);
        }
    }
    __syncthreads();
    if (tid < 2 * FF) atomicAdd(&d_bn[tid], sh_bna[tid]);
}

// final-layer BN + relu + global_add_pool
__global__ void k_bnpool(const float* __restrict__ gamma, const float* __restrict__ beta,
                         const int* __restrict__ batch, int l) {
    int n = blockIdx.x * blockDim.x + threadIdx.x;
    if (n >= NN) return;
    int b = batch[n];
    if (b < 0) b = 0;
    if (b >= GG) b = GG - 1;
#pragma unroll
    for (int f = 0; f < FF; f++) {
        float mu  = d_bn[f] / (float)NN;
        float var = d_bn[FF + f] / (float)NN - mu * mu;
        float v = (d_o[n * FF + f] - mu) * rsqrtf(var + 1e-5f)
                  * __ldg(&gamma[l * FF + f]) + __ldg(&beta[l * FF + f]);
        v = fmaxf(v, 0.f);
        atomicAdd(&d_pool[b * FF + f], v);
    }
}

__global__ void k_final(const float* __restrict__ w1, const float* __restrict__ b1,
                        const float* __restrict__ w2, const float* __restrict__ b2,
                        float* __restrict__ out) {
    int g = threadIdx.x;
    if (g >= GG) return;
    float pv[FF];
#pragma unroll
    for (int k = 0; k < FF; k++) pv[k] = d_pool[g * FF + k];
    float o = b2[0];
#pragma unroll
    for (int j = 0; j < 5; j++) {
        float hj = b1[j];
#pragma unroll
        for (int k = 0; k < FF; k++) hj += pv[k] * w1[k * 5 + j];
        o += fmaxf(hj, 0.f) * w2[j];
    }
    out[g] = o;
}

// ---------------- launch -----------------------------------------------------
extern "C" void kernel_launch(void* const* d_in, const int* in_sizes, int n_in,
                              void* d_out, int out_size) {
    const float* x        = (const float*)d_in[0];
    const float* edge_emb = (const float*)d_in[1];
    const float* mlp1_w1  = (const float*)d_in[2];
    const float* mlp1_b1  = (const float*)d_in[3];
    const float* mlp1_w2  = (const float*)d_in[4];
    const float* mlp1_b2  = (const float*)d_in[5];
    const float* enc_w    = (const float*)d_in[6];
    const float* enc_b    = (const float*)d_in[7];
    const float* pre_w    = (const float*)d_in[8];
    const float* pre_b    = (const float*)d_in[9];
    const float* post_w   = (const float*)d_in[10];
    const float* post_b   = (const float*)d_in[11];
    const float* lin_w    = (const float*)d_in[12];
    const float* lin_b    = (const float*)d_in[13];
    const float* bn_gamma = (const float*)d_in[14];
    const float* bn_beta  = (const float*)d_in[15];
    const float* mlp2_w1  = (const float*)d_in[16];
    const float* mlp2_b1  = (const float*)d_in[17];
    const float* mlp2_w2  = (const float*)d_in[18];
    const float* mlp2_b2  = (const float*)d_in[19];
    const int* edge_index = (const int*)d_in[20];
    const int* edge_attr  = (const int*)d_in[21];
    const int* batch      = (const int*)d_in[22];
    float* out = (float*)d_out;

    const int TB = 256;
    k_zero<<<(NN + TB - 1) / TB, TB>>>();
    k_deg<<<(NE + TB - 1) / TB, TB>>>(edge_index);
    k_scan<<<1, 1024>>>();
    k_fill<<<(NE + TB - 1) / TB, TB>>>(edge_index, edge_attr);
    // layer 0
    k_etab<<<1, 256>>>(edge_emb, enc_w, enc_b, pre_w, pre_b, 0);
    k_pq<<<(NN + 3) / 4, 256>>>(x, mlp1_w1, mlp1_b1, mlp1_w2, mlp1_b2,
                                bn_gamma, bn_beta, pre_w, 0, 0);
    k_agg<<<(NN + 7) / 8, 256>>>(post_w, post_b, lin_w, lin_b, 0);
    // layer 1 (k_pq reads layer-0 BN sums BEFORE k_etab resets d_bn)
    k_pq<<<(NN + 3) / 4, 256>>>(x, mlp1_w1, mlp1_b1, mlp1_w2, mlp1_b2,
                                bn_gamma, bn_beta, pre_w, 1, 1);
    k_etab<<<1, 256>>>(edge_emb, enc_w, enc_b, pre_w, pre_b, 1);
    k_agg<<<(NN + 7) / 8, 256>>>(post_w, post_b, lin_w, lin_b, 1);
    k_bnpool<<<(NN + TB - 1) / TB, TB>>>(bn_gamma, bn_beta, batch, 1);
    k_final<<<1, 64>>>(mlp2_w1, mlp2_b1, mlp2_w2, mlp2_b2, out);
}